// round 14
// baseline (speedup 1.0000x reference)
#include <cuda_runtime.h>
#include <cuda_bf16.h>
#include <cstdint>

#define FDIM 128
#define CDIM 132
#define KBE  136          // padded K in bf16 elements
#define RSTR 272          // bytes per smem row of W (136 bf16)
#define XRSW 136          // x smem row stride in floats (544 B)
#define TILE 192
#define NTHR 256

// smem byte offsets
#define SM_BS   0                           // bias: 136 floats (pad to 1024)
#define SM_B1S  1024                        // b1 buffer: 192 x 4 floats -> 3072
#define SM_DC   4096                        // d_chi f32: 192 x 8 floats = 6144
#define SM_XS   10240                       // x f32: 192 x 544 = 104448
#define SM_WH   114688
#define SM_WL   (SM_WH + KBE * RSTR)        // 151680
#define SMEM_BYTES (SM_WL + KBE * RSTR)     // 188672

static __device__ __forceinline__ uint32_t smem_u32(const void* p) {
    uint32_t a;
    asm("{ .reg .u64 t; cvta.to.shared.u64 t, %1; cvt.u32.u64 %0, t; }" : "=r"(a) : "l"(p));
    return a;
}
static __device__ __forceinline__ void split(float v, unsigned short& h, unsigned short& l) {
    __nv_bfloat16 hb = __float2bfloat16(v);
    float r = v - __bfloat162float(hb);
    __nv_bfloat16 lb = __float2bfloat16(r);
    h = __bfloat16_as_ushort(hb);
    l = __bfloat16_as_ushort(lb);
}
// packed split: a -> lower half, b -> upper half
static __device__ __forceinline__ void sp2(float a, float b, uint32_t& h, uint32_t& l) {
    uint32_t hp;
    asm("cvt.rn.bf16x2.f32 %0, %1, %2;" : "=r"(hp) : "f"(b), "f"(a));
    float ha = __uint_as_float(hp << 16);
    float hb = __uint_as_float(hp & 0xFFFF0000u);
    float la = a - ha;
    float lb = b - hb;
    uint32_t lp;
    asm("cvt.rn.bf16x2.f32 %0, %1, %2;" : "=r"(lp) : "f"(lb), "f"(la));
    h = hp; l = lp;
}

static __device__ __forceinline__ void ldsm4(uint32_t a, uint32_t* r) {
    asm volatile("ldmatrix.sync.aligned.m8n8.x4.shared.b16 {%0,%1,%2,%3}, [%4];"
        : "=r"(r[0]), "=r"(r[1]), "=r"(r[2]), "=r"(r[3]) : "r"(a));
}
static __device__ __forceinline__ void ldsm2(uint32_t a, uint32_t* r) {
    asm volatile("ldmatrix.sync.aligned.m8n8.x2.shared.b16 {%0,%1}, [%2];"
        : "=r"(r[0]), "=r"(r[1]) : "r"(a));
}
static __device__ __forceinline__ void ldsm1(uint32_t a, uint32_t* r) {
    asm volatile("ldmatrix.sync.aligned.m8n8.x1.shared.b16 {%0}, [%1];"
        : "=r"(r[0]) : "r"(a));
}
static __device__ __forceinline__ void mma16(float* c, const uint32_t* A, const uint32_t* B) {
    asm volatile("mma.sync.aligned.m16n8k16.row.col.f32.bf16.bf16.f32 "
        "{%0,%1,%2,%3}, {%4,%5,%6,%7}, {%8,%9}, {%0,%1,%2,%3};"
        : "+f"(c[0]), "+f"(c[1]), "+f"(c[2]), "+f"(c[3])
        : "r"(A[0]), "r"(A[1]), "r"(A[2]), "r"(A[3]), "r"(B[0]), "r"(B[1]));
}
static __device__ __forceinline__ void mma8(float* c, const uint32_t* A, uint32_t B) {
    asm volatile("mma.sync.aligned.m16n8k8.row.col.f32.bf16.bf16.f32 "
        "{%0,%1,%2,%3}, {%4,%5}, {%6}, {%0,%1,%2,%3};"
        : "+f"(c[0]), "+f"(c[1]), "+f"(c[2]), "+f"(c[3])
        : "r"(A[0]), "r"(A[1]), "r"(B));
}

struct Offs {
    uint32_t bpo[4];     // B x4 pair offsets (k16)
    uint32_t b16s;       // B x2 single-group offset (NG odd)
    uint32_t b8po[4];    // B x2 pair offsets (k8 tail)
    uint32_t b8s;        // B x1 single-group offset (k8 tail, NG odd)
};

// One k16 step: A from f32 smem via conflict-free LDS.64 + inline hi/lo split,
// B via ldmatrix from W smem; 3 products (hi*hi + hi*lo + lo*hi).
template<int NG>
static __device__ __forceinline__ void k16_step(
    int s, const float* const* ax, uint32_t whb, uint32_t wlb,
    const Offs& o, float (*acc)[4])
{
    const uint32_t kb = (uint32_t)s * 32;
    const int xo = s * 16;
    float2 raw[3][4];
    #pragma unroll
    for (int f = 0; f < 3; ++f) {
        raw[f][0] = *(const float2*)(ax[2*f]   + xo);
        raw[f][1] = *(const float2*)(ax[2*f+1] + xo);
        raw[f][2] = *(const float2*)(ax[2*f]   + xo + 8);
        raw[f][3] = *(const float2*)(ax[2*f+1] + xo + 8);
    }
    uint32_t Bh[NG][2], Bl[NG][2];
    #pragma unroll
    for (int p = 0; p < NG / 2; ++p) {
        uint32_t r[4];
        ldsm4(whb + o.bpo[p] + kb, r);
        Bh[2*p][0] = r[0]; Bh[2*p][1] = r[1];
        Bh[2*p+1][0] = r[2]; Bh[2*p+1][1] = r[3];
        ldsm4(wlb + o.bpo[p] + kb, r);
        Bl[2*p][0] = r[0]; Bl[2*p][1] = r[1];
        Bl[2*p+1][0] = r[2]; Bl[2*p+1][1] = r[3];
    }
    if (NG & 1) {
        ldsm2(whb + o.b16s + kb, Bh[NG-1]);
        ldsm2(wlb + o.b16s + kb, Bl[NG-1]);
    }
    uint32_t Ah[3][4], Al[3][4];
    #pragma unroll
    for (int f = 0; f < 3; ++f)
        #pragma unroll
        for (int j = 0; j < 4; ++j)
            sp2(raw[f][j].x, raw[f][j].y, Ah[f][j], Al[f][j]);
    #pragma unroll
    for (int f = 0; f < 3; ++f)
        #pragma unroll
        for (int g = 0; g < NG; ++g)
            mma16(acc[f * NG + g], Ah[f], Bh[g]);
    #pragma unroll
    for (int f = 0; f < 3; ++f)
        #pragma unroll
        for (int g = 0; g < NG; ++g)
            mma16(acc[f * NG + g], Ah[f], Bl[g]);
    #pragma unroll
    for (int f = 0; f < 3; ++f)
        #pragma unroll
        for (int g = 0; g < NG; ++g)
            mma16(acc[f * NG + g], Al[f], Bh[g]);
}

template<int CW>
static __device__ __forceinline__ void compute_tile(
    const float* const* ax, const float* dc,
    uint32_t whb, uint32_t wlb, const Offs& o, const float* bs, float* b1s,
    float* __restrict__ a1, long long row0, long long n,
    int mrow, int qr, int qc)
{
    constexpr int NG = CW ? 8 : 9;
    constexpr int G0 = CW ? 9 : 0;

    float acc[3 * NG][4];
    #pragma unroll
    for (int i = 0; i < 3 * NG; ++i)
        #pragma unroll
        for (int j = 0; j < 4; ++j) acc[i][j] = 0.f;

    #pragma unroll
    for (int s = 0; s < 8; ++s)
        k16_step<NG>(s, ax, whb, wlb, o, acc);

    // ---- k8 tail: k = 128..135, A from d_chi f32 smem ----
    {
        uint32_t Ah[3][2], Al[3][2];
        #pragma unroll
        for (int f = 0; f < 3; ++f) {
            int r = mrow + f * 16 + qr;
            float2 v0 = *(const float2*)(dc + r * 8 + 2 * qc);
            float2 v1 = *(const float2*)(dc + (r + 8) * 8 + 2 * qc);
            sp2(v0.x, v0.y, Ah[f][0], Al[f][0]);
            sp2(v1.x, v1.y, Ah[f][1], Al[f][1]);
        }
        uint32_t B8h[NG], B8l[NG];
        #pragma unroll
        for (int p = 0; p < NG / 2; ++p) {
            uint32_t r[2];
            ldsm2(whb + o.b8po[p], r);
            B8h[2*p] = r[0]; B8h[2*p+1] = r[1];
            ldsm2(wlb + o.b8po[p], r);
            B8l[2*p] = r[0]; B8l[2*p+1] = r[1];
        }
        if (NG & 1) {
            uint32_t r[1];
            ldsm1(whb + o.b8s, r); B8h[NG-1] = r[0];
            ldsm1(wlb + o.b8s, r); B8l[NG-1] = r[0];
        }
        #pragma unroll
        for (int f = 0; f < 3; ++f) {
            #pragma unroll
            for (int g = 0; g < NG; ++g) {
                mma8(acc[f * NG + g], Ah[f], B8h[g]);
                mma8(acc[f * NG + g], Ah[f], B8l[g]);
                mma8(acc[f * NG + g], Al[f], B8h[g]);
            }
        }
    }

    // ---- epilogue ----
    #pragma unroll
    for (int f = 0; f < 3; ++f) {
        #pragma unroll
        for (int g = 0; g < NG; ++g) {
            const int ga = G0 + g;
            const float* ac = acc[f * NG + g];
            const int colg = ga * 8 + qc * 2;
            if (ga < 16) {
                float bx = bs[colg], by = bs[colg + 1];
                long long r1 = row0 + mrow + f * 16 + qr;
                if (r1 < n)
                    *(float2*)(a1 + r1 * FDIM + colg) = make_float2(ac[0] + bx, ac[1] + by);
                if (r1 + 8 < n)
                    *(float2*)(a1 + (r1 + 8) * FDIM + colg) = make_float2(ac[2] + bx, ac[3] + by);
            } else if (ga == 16) {
                if (qc < 2) {
                    int l = qc * 2;
                    float bx = bs[FDIM + l], by = bs[FDIM + l + 1];
                    int rl = mrow + f * 16 + qr;
                    b1s[rl * 4 + l]       = ac[0] + bx;
                    b1s[rl * 4 + l + 1]   = ac[1] + by;
                    b1s[(rl + 8) * 4 + l]     = ac[2] + bx;
                    b1s[(rl + 8) * 4 + l + 1] = ac[3] + by;
                }
            }
        }
    }
}

// ---- x staging: pure coalesced f32 copy (no conversion) ----
static __device__ __forceinline__ void stage_x(
    const float* __restrict__ x, char* sm, long long row0, long long n, int tid)
{
    float* xs = (float*)(sm + SM_XS);
    #pragma unroll
    for (int i = 0; i < 24; ++i) {
        int idx = i * NTHR + tid;          // 16B chunk id, 0..6143
        int row = idx >> 5;
        int ch  = idx & 31;
        long long r = row0 + row;
        float4 v = (r < n) ? *(const float4*)(x + r * FDIM + ch * 4)
                           : make_float4(0.f, 0.f, 0.f, 0.f);
        *(float4*)(xs + row * XRSW + ch * 4) = v;
    }
}

// ---- d_chi staging (f32, 8-wide zero-padded): threads 0..191 cover rows ----
static __device__ __forceinline__ void stage_dchi(
    const float* __restrict__ chi, char* sm, long long row, bool ok, int rloc)
{
    float c[16];
    #pragma unroll
    for (int q = 0; q < 4; ++q) {
        float4 v = ok ? *(const float4*)(chi + row * 16 + q * 4)
                      : make_float4(0.f, 0.f, 0.f, 0.f);
        c[q*4+0] = v.x; c[q*4+1] = v.y; c[q*4+2] = v.z; c[q*4+3] = v.w;
    }
    float s0 = c[0] * c[0];
    float s1 = c[1]*c[1] + c[2]*c[2] + c[3]*c[3];
    float s2 = 0.f, s3 = 0.f;
    #pragma unroll
    for (int m = 4; m < 9; ++m)  s2 += c[m] * c[m];
    #pragma unroll
    for (int m = 9; m < 16; ++m) s3 += c[m] * c[m];
    float* dc = (float*)(sm + SM_DC);
    *(float4*)(dc + rloc * 8)     = make_float4(s0, s1, s2, s3);
    *(float4*)(dc + rloc * 8 + 4) = make_float4(0.f, 0.f, 0.f, 0.f);
}

// ---- chi_out: threads 0..191 cover rows; reloads chi (L2-warm) ----
static __device__ __forceinline__ void chi_out_store(
    float* __restrict__ co, const float* __restrict__ chi, const float* b1s,
    long long row, bool ok, int rloc)
{
    if (!ok) return;
    float4 bv = ((const float4*)b1s)[rloc];
    float c[16];
    #pragma unroll
    for (int q = 0; q < 4; ++q) {
        float4 v = *(const float4*)(chi + row * 16 + q * 4);
        c[q*4+0] = v.x; c[q*4+1] = v.y; c[q*4+2] = v.z; c[q*4+3] = v.w;
    }
    float o8[16];
    o8[0] = bv.x * c[0];
    #pragma unroll
    for (int m = 1; m < 4; ++m)  o8[m] = bv.y * c[m];
    #pragma unroll
    for (int m = 4; m < 9; ++m)  o8[m] = bv.z * c[m];
    #pragma unroll
    for (int m = 9; m < 16; ++m) o8[m] = bv.w * c[m];
    float4* dst = (float4*)(co + row * 16);
    #pragma unroll
    for (int q = 0; q < 4; ++q)
        dst[q] = make_float4(o8[q*4], o8[q*4+1], o8[q*4+2], o8[q*4+3]);
}

__global__ void __launch_bounds__(NTHR, 1)
ib_mma(const float* __restrict__ x, const float* __restrict__ chi,
       const float* __restrict__ W, const float* __restrict__ b,
       float* __restrict__ a1, float* __restrict__ co,
       long long n, long long T)
{
    extern __shared__ char sm[];
    float* bs  = (float*)(sm + SM_BS);
    float* b1s = (float*)(sm + SM_B1S);
    unsigned short* whp = (unsigned short*)(sm + SM_WH);
    unsigned short* wlp = (unsigned short*)(sm + SM_WL);

    const int tid = threadIdx.x, wid = tid >> 5, lane = tid & 31;
    const uint32_t smb = smem_u32(sm);
    const uint32_t whb = smb + SM_WH, wlb = smb + SM_WL;

    // ---- stage W^T (hi/lo bf16) + bias, once ----
    for (int i = tid; i < KBE * KBE; i += NTHR) {
        int nn = i % KBE, kk = i / KBE;
        float w = (nn < CDIM && kk < CDIM) ? W[kk * CDIM + nn] : 0.f;
        unsigned short h, l;
        split(w, h, l);
        whp[nn * KBE + kk] = h;
        wlp[nn * KBE + kk] = l;
    }
    for (int i = tid; i < KBE; i += NTHR) bs[i] = (i < CDIM) ? b[i] : 0.f;

    // ---- per-warp layout (4M x 2N grid, M=48/warp) ----
    const int mrow = (wid & 3) * 48;
    const int cw   = wid >> 2;
    const int j3 = lane >> 3, rw = lane & 7;
    const int qr = lane >> 2, qc = lane & 3;
    const int g0 = cw ? 9 : 0;

    Offs o;
    #pragma unroll
    for (int p = 0; p < 4; ++p) {
        int g = g0 + 2 * p;
        o.bpo[p]  = (uint32_t)((g * 8 + ((j3 >> 1) << 3) + rw) * RSTR + ((j3 & 1) << 4));
        o.b8po[p] = (uint32_t)((g * 8 + ((j3 & 1) << 3) + rw) * RSTR + 256);
    }
    o.b16s = (uint32_t)((64 + rw) * RSTR + ((j3 & 1) << 4));
    o.b8s  = (uint32_t)((64 + rw) * RSTR + 256);

    // A fragment smem row pointers (f32): ax[2f+h] = row mrow + f*16 + h*8 + qr
    const float* ax[6];
    {
        const float* xs = (const float*)(sm + SM_XS);
        #pragma unroll
        for (int f = 0; f < 3; ++f)
            #pragma unroll
            for (int h = 0; h < 2; ++h)
                ax[2*f + h] = xs + (mrow + f * 16 + h * 8 + qr) * XRSW + qc * 2;
    }
    const float* dc = (const float*)(sm + SM_DC);
    const int grid = gridDim.x;

    // ---- preamble: stage first tile ----
    {
        long long row0 = blockIdx.x * (long long)TILE;
        stage_x(x, sm, row0, n, tid);
        if (tid < TILE)
            stage_dchi(chi, sm, row0 + tid, row0 + tid < n, tid);
    }
    __syncthreads();

    for (long long t = blockIdx.x; t < T; t += grid) {
        const long long row0 = t * TILE;

        // ---- MMA + a1/b1 epilogue ----
        if (cw == 0)
            compute_tile<0>(ax, dc, whb, wlb, o, bs, b1s, a1, row0, n, mrow, qr, qc);
        else
            compute_tile<1>(ax, dc, whb, wlb, o, bs, b1s, a1, row0, n, mrow, qr, qc);
        __syncthreads();

        // ---- stage(t+grid) + chi_out(t) in one phase ----
        const long long t2 = t + grid;
        if (t2 < T) {
            long long r2 = t2 * TILE;
            stage_x(x, sm, r2, n, tid);
            if (tid < TILE)
                stage_dchi(chi, sm, r2 + tid, r2 + tid < n, tid);
        }
        if (tid < TILE)
            chi_out_store(co, chi, b1s, row0 + tid, row0 + tid < n, tid);
        __syncthreads();
    }
}

extern "C" void kernel_launch(void* const* d_in, const int* in_sizes, int n_in,
                              void* d_out, int out_size)
{
    int ix = 0, ichi = 1, iW = 3, ib_ = 4;
    long long maxsz = -1;
    for (int i = 0; i < n_in; ++i)
        if ((long long)in_sizes[i] > maxsz) { maxsz = in_sizes[i]; ix = i; }
    long long n = maxsz / FDIM;
    for (int i = 0; i < n_in; ++i) {
        long long s = in_sizes[i];
        if (i == ix) continue;
        if (s == CDIM * CDIM) iW = i;
        else if (s == CDIM)   ib_ = i;
        else if (s == 16 * n) ichi = i;
    }
    const float* x   = (const float*)d_in[ix];
    const float* chi = (const float*)d_in[ichi];
    const float* W   = (const float*)d_in[iW];
    const float* b   = (const float*)d_in[ib_];
    float* a1 = (float*)d_out;
    float* co = a1 + (size_t)n * FDIM;

    long long T = (n + TILE - 1) / TILE;
    int sms = 148;
    cudaDeviceGetAttribute(&sms, cudaDevAttrMultiProcessorCount, 0);
    int grid = (int)(T < sms ? T : sms);

    cudaFuncSetAttribute(ib_mma, cudaFuncAttributeMaxDynamicSharedMemorySize, SMEM_BYTES);
    ib_mma<<<grid, NTHR, SMEM_BYTES>>>(x, chi, W, b, a1, co, n, T);
}

// round 15
// speedup vs baseline: 1.2251x; 1.2251x over previous
#include <cuda_runtime.h>
#include <cuda_bf16.h>
#include <cstdint>

#define FDIM 128
#define CDIM 132
#define KBE  136          // padded K in bf16 elements
#define RSTR 272          // bytes per smem row of W (136 bf16)
#define TILE 128
#define NTHR 128

// smem byte offsets (per block)
#define SM_BS   0                           // bias: 136 floats
#define SM_B1S  1024                        // b1 double buffer: 2 x 2048
#define SM_DC   5120                        // d_chi f32 double buffer: 2 x 4096
#define SM_WH   13312
#define SM_WL   (SM_WH + KBE * RSTR)        // 50304
#define SMEM_BYTES (SM_WL + KBE * RSTR)     // 87296  (x2 blocks = 174592)

static __device__ __forceinline__ uint32_t smem_u32(const void* p) {
    uint32_t a;
    asm("{ .reg .u64 t; cvta.to.shared.u64 t, %1; cvt.u32.u64 %0, t; }" : "=r"(a) : "l"(p));
    return a;
}
static __device__ __forceinline__ void split(float v, unsigned short& h, unsigned short& l) {
    __nv_bfloat16 hb = __float2bfloat16(v);
    float r = v - __bfloat162float(hb);
    __nv_bfloat16 lb = __float2bfloat16(r);
    h = __bfloat16_as_ushort(hb);
    l = __bfloat16_as_ushort(lb);
}
// packed split: a -> lower half, b -> upper half
static __device__ __forceinline__ void sp2(float a, float b, uint32_t& h, uint32_t& l) {
    uint32_t hp;
    asm("cvt.rn.bf16x2.f32 %0, %1, %2;" : "=r"(hp) : "f"(b), "f"(a));
    float ha = __uint_as_float(hp << 16);
    float hb = __uint_as_float(hp & 0xFFFF0000u);
    float la = a - ha;
    float lb = b - hb;
    uint32_t lp;
    asm("cvt.rn.bf16x2.f32 %0, %1, %2;" : "=r"(lp) : "f"(lb), "f"(la));
    h = hp; l = lp;
}

static __device__ __forceinline__ void ldsm4(uint32_t a, uint32_t* r) {
    asm volatile("ldmatrix.sync.aligned.m8n8.x4.shared.b16 {%0,%1,%2,%3}, [%4];"
        : "=r"(r[0]), "=r"(r[1]), "=r"(r[2]), "=r"(r[3]) : "r"(a));
}
static __device__ __forceinline__ void ldsm2(uint32_t a, uint32_t* r) {
    asm volatile("ldmatrix.sync.aligned.m8n8.x2.shared.b16 {%0,%1}, [%2];"
        : "=r"(r[0]), "=r"(r[1]) : "r"(a));
}
static __device__ __forceinline__ void ldsm1(uint32_t a, uint32_t* r) {
    asm volatile("ldmatrix.sync.aligned.m8n8.x1.shared.b16 {%0}, [%1];"
        : "=r"(r[0]) : "r"(a));
}
static __device__ __forceinline__ void mma16(float* c, const uint32_t* A, const uint32_t* B) {
    asm volatile("mma.sync.aligned.m16n8k16.row.col.f32.bf16.bf16.f32 "
        "{%0,%1,%2,%3}, {%4,%5,%6,%7}, {%8,%9}, {%0,%1,%2,%3};"
        : "+f"(c[0]), "+f"(c[1]), "+f"(c[2]), "+f"(c[3])
        : "r"(A[0]), "r"(A[1]), "r"(A[2]), "r"(A[3]), "r"(B[0]), "r"(B[1]));
}
static __device__ __forceinline__ void mma8(float* c, const uint32_t* A, uint32_t B) {
    asm volatile("mma.sync.aligned.m16n8k8.row.col.f32.bf16.bf16.f32 "
        "{%0,%1,%2,%3}, {%4,%5}, {%6}, {%0,%1,%2,%3};"
        : "+f"(c[0]), "+f"(c[1]), "+f"(c[2]), "+f"(c[3])
        : "r"(A[0]), "r"(A[1]), "r"(B));
}

struct Offs {
    uint32_t bpo[4];     // B x4 pair offsets (k16)
    uint32_t b16s;       // B x2 single-group offset (NG odd)
    uint32_t b8po[4];    // B x2 pair offsets (k8 tail)
    uint32_t b8s;        // B x1 single-group offset (k8 tail, NG odd)
};
struct ARow { const float* p[8]; };  // clamped row pointers (+4*qc)

// One k16 step. A: one float4 per row-half (k-permuted so the 4 values land in
// this thread's fragment slots). B: streamed pair-by-pair to keep regs low.
template<int NG>
static __device__ __forceinline__ void k16_step(
    int s, const ARow& ar, uint32_t whb, uint32_t wlb,
    const Offs& o, float (*acc)[4])
{
    const uint32_t kb = (uint32_t)s * 32;
    const int xo = s * 16;
    uint32_t Ah[4][4], Al[4][4];
    #pragma unroll
    for (int f = 0; f < 4; ++f) {
        float4 v0 = *(const float4*)(ar.p[2*f]   + xo);
        float4 v1 = *(const float4*)(ar.p[2*f+1] + xo);
        sp2(v0.x, v0.y, Ah[f][0], Al[f][0]);
        sp2(v1.x, v1.y, Ah[f][1], Al[f][1]);
        sp2(v0.z, v0.w, Ah[f][2], Al[f][2]);
        sp2(v1.z, v1.w, Ah[f][3], Al[f][3]);
    }
    #pragma unroll
    for (int p = 0; p < NG / 2; ++p) {
        uint32_t r[4];
        ldsm4(whb + o.bpo[p] + kb, r);
        #pragma unroll
        for (int f = 0; f < 4; ++f) {
            mma16(acc[f * NG + 2*p],     Ah[f], r);
            mma16(acc[f * NG + 2*p + 1], Ah[f], r + 2);
            mma16(acc[f * NG + 2*p],     Al[f], r);
            mma16(acc[f * NG + 2*p + 1], Al[f], r + 2);
        }
        ldsm4(wlb + o.bpo[p] + kb, r);
        #pragma unroll
        for (int f = 0; f < 4; ++f) {
            mma16(acc[f * NG + 2*p],     Ah[f], r);
            mma16(acc[f * NG + 2*p + 1], Ah[f], r + 2);
        }
    }
    if (NG & 1) {
        uint32_t r[2];
        ldsm2(whb + o.b16s + kb, r);
        #pragma unroll
        for (int f = 0; f < 4; ++f) {
            mma16(acc[f * NG + NG - 1], Ah[f], r);
            mma16(acc[f * NG + NG - 1], Al[f], r);
        }
        ldsm2(wlb + o.b16s + kb, r);
        #pragma unroll
        for (int f = 0; f < 4; ++f)
            mma16(acc[f * NG + NG - 1], Ah[f], r);
    }
}

template<int CW>
static __device__ __forceinline__ void compute_tile(
    const ARow& ar, const float* dc,
    uint32_t whb, uint32_t wlb, const Offs& o, const float* bs, float* b1s,
    float* __restrict__ a1, long long row0, long long n,
    int mrow, int qr, int qc)
{
    constexpr int NG = CW ? 8 : 9;
    constexpr int G0 = CW ? 9 : 0;

    float acc[4 * NG][4];
    #pragma unroll
    for (int i = 0; i < 4 * NG; ++i)
        #pragma unroll
        for (int j = 0; j < 4; ++j) acc[i][j] = 0.f;

    #pragma unroll
    for (int s = 0; s < 8; ++s)
        k16_step<NG>(s, ar, whb, wlb, o, acc);

    // ---- k8 tail: k = 128..135 (identity k-map), A from d_chi f32 smem ----
    {
        uint32_t Ah[4][2], Al[4][2];
        #pragma unroll
        for (int f = 0; f < 4; ++f) {
            int r = mrow + f * 16 + qr;
            float2 v0 = *(const float2*)(dc + r * 8 + 2 * qc);
            float2 v1 = *(const float2*)(dc + (r + 8) * 8 + 2 * qc);
            sp2(v0.x, v0.y, Ah[f][0], Al[f][0]);
            sp2(v1.x, v1.y, Ah[f][1], Al[f][1]);
        }
        #pragma unroll
        for (int p = 0; p < NG / 2; ++p) {
            uint32_t r[2];
            ldsm2(whb + o.b8po[p], r);
            #pragma unroll
            for (int f = 0; f < 4; ++f) {
                mma8(acc[f * NG + 2*p],     Ah[f], r[0]);
                mma8(acc[f * NG + 2*p + 1], Ah[f], r[1]);
                mma8(acc[f * NG + 2*p],     Al[f], r[0]);
                mma8(acc[f * NG + 2*p + 1], Al[f], r[1]);
            }
            ldsm2(wlb + o.b8po[p], r);
            #pragma unroll
            for (int f = 0; f < 4; ++f) {
                mma8(acc[f * NG + 2*p],     Ah[f], r[0]);
                mma8(acc[f * NG + 2*p + 1], Ah[f], r[1]);
            }
        }
        if (NG & 1) {
            uint32_t r[1];
            ldsm1(whb + o.b8s, r);
            #pragma unroll
            for (int f = 0; f < 4; ++f) {
                mma8(acc[f * NG + NG - 1], Ah[f], r[0]);
                mma8(acc[f * NG + NG - 1], Al[f], r[0]);
            }
            ldsm1(wlb + o.b8s, r);
            #pragma unroll
            for (int f = 0; f < 4; ++f)
                mma8(acc[f * NG + NG - 1], Ah[f], r[0]);
        }
    }

    // ---- epilogue ----
    #pragma unroll
    for (int f = 0; f < 4; ++f) {
        #pragma unroll
        for (int g = 0; g < NG; ++g) {
            const int ga = G0 + g;
            const float* ac = acc[f * NG + g];
            const int colg = ga * 8 + qc * 2;
            if (ga < 16) {
                float bx = bs[colg], by = bs[colg + 1];
                long long r1 = row0 + mrow + f * 16 + qr;
                if (r1 < n)
                    *(float2*)(a1 + r1 * FDIM + colg) = make_float2(ac[0] + bx, ac[1] + by);
                if (r1 + 8 < n)
                    *(float2*)(a1 + (r1 + 8) * FDIM + colg) = make_float2(ac[2] + bx, ac[3] + by);
            } else if (ga == 16) {
                if (qc < 2) {
                    int l = qc * 2;
                    float bx = bs[FDIM + l], by = bs[FDIM + l + 1];
                    int rl = mrow + f * 16 + qr;
                    b1s[rl * 4 + l]       = ac[0] + bx;
                    b1s[rl * 4 + l + 1]   = ac[1] + by;
                    b1s[(rl + 8) * 4 + l]     = ac[2] + bx;
                    b1s[(rl + 8) * 4 + l + 1] = ac[3] + by;
                }
            }
        }
    }
}

// ---- d_chi staging (f32, 8-wide zero-padded): thread tid covers row tid ----
static __device__ __forceinline__ void stage_dchi(
    const float* __restrict__ chi, char* sm, uint32_t dcoff,
    long long row, bool ok, int rloc)
{
    float c[16];
    #pragma unroll
    for (int q = 0; q < 4; ++q) {
        float4 v = ok ? *(const float4*)(chi + row * 16 + q * 4)
                      : make_float4(0.f, 0.f, 0.f, 0.f);
        c[q*4+0] = v.x; c[q*4+1] = v.y; c[q*4+2] = v.z; c[q*4+3] = v.w;
    }
    float s0 = c[0] * c[0];
    float s1 = c[1]*c[1] + c[2]*c[2] + c[3]*c[3];
    float s2 = 0.f, s3 = 0.f;
    #pragma unroll
    for (int m = 4; m < 9; ++m)  s2 += c[m] * c[m];
    #pragma unroll
    for (int m = 9; m < 16; ++m) s3 += c[m] * c[m];
    float* dc = (float*)(sm + dcoff);
    *(float4*)(dc + rloc * 8)     = make_float4(s0, s1, s2, s3);
    *(float4*)(dc + rloc * 8 + 4) = make_float4(0.f, 0.f, 0.f, 0.f);
}

// ---- chi_out: thread tid covers row tid; reloads chi (L2-warm) ----
static __device__ __forceinline__ void chi_out_store(
    float* __restrict__ co, const float* __restrict__ chi, const float* b1s,
    long long row, bool ok, int rloc)
{
    if (!ok) return;
    float4 bv = ((const float4*)b1s)[rloc];
    float c[16];
    #pragma unroll
    for (int q = 0; q < 4; ++q) {
        float4 v = *(const float4*)(chi + row * 16 + q * 4);
        c[q*4+0] = v.x; c[q*4+1] = v.y; c[q*4+2] = v.z; c[q*4+3] = v.w;
    }
    float o8[16];
    o8[0] = bv.x * c[0];
    #pragma unroll
    for (int m = 1; m < 4; ++m)  o8[m] = bv.y * c[m];
    #pragma unroll
    for (int m = 4; m < 9; ++m)  o8[m] = bv.z * c[m];
    #pragma unroll
    for (int m = 9; m < 16; ++m) o8[m] = bv.w * c[m];
    float4* dst = (float4*)(co + row * 16);
    #pragma unroll
    for (int q = 0; q < 4; ++q)
        dst[q] = make_float4(o8[q*4], o8[q*4+1], o8[q*4+2], o8[q*4+3]);
}

__global__ void __launch_bounds__(NTHR, 2)
ib_mma(const float* __restrict__ x, const float* __restrict__ chi,
       const float* __restrict__ W, const float* __restrict__ b,
       float* __restrict__ a1, float* __restrict__ co,
       long long n, long long T)
{
    extern __shared__ char sm[];
    float* bs = (float*)(sm + SM_BS);
    unsigned short* whp = (unsigned short*)(sm + SM_WH);
    unsigned short* wlp = (unsigned short*)(sm + SM_WL);

    const int tid = threadIdx.x, wid = tid >> 5, lane = tid & 31;
    const uint32_t smb = smem_u32(sm);
    const uint32_t whb = smb + SM_WH, wlb = smb + SM_WL;

    // ---- stage W^T (hi/lo bf16, K-PERMUTED) + bias, once ----
    // logical k L (block s, offset o=4q+j) -> phys p = s*16 + 2q + (j&1) + 8*(j>>1)
    for (int i = tid; i < KBE * KBE; i += NTHR) {
        int nn = i % KBE, kk = i / KBE;
        float w = (nn < CDIM && kk < CDIM) ? W[kk * CDIM + nn] : 0.f;
        int pp;
        if (kk < FDIM) {
            int s = kk >> 4, oo = kk & 15;
            pp = s * 16 + ((oo >> 2) << 1) + (oo & 1) + (((oo >> 1) & 1) << 3);
        } else pp = kk;   // tail keeps identity
        unsigned short h, l;
        split(w, h, l);
        whp[nn * KBE + pp] = h;
        wlp[nn * KBE + pp] = l;
    }
    for (int i = tid; i < KBE; i += NTHR) bs[i] = (i < CDIM) ? b[i] : 0.f;

    // ---- per-warp layout (2M x 2N grid, M=64/warp) ----
    const int mrow = (wid & 1) * 64;
    const int cw   = wid >> 1;
    const int j3 = lane >> 3, rw = lane & 7;
    const int qr = lane >> 2, qc = lane & 3;
    const int g0 = cw ? 9 : 0;

    Offs o;
    #pragma unroll
    for (int p = 0; p < 4; ++p) {
        int g = g0 + 2 * p;
        o.bpo[p]  = (uint32_t)((g * 8 + ((j3 >> 1) << 3) + rw) * RSTR + ((j3 & 1) << 4));
        o.b8po[p] = (uint32_t)((g * 8 + ((j3 & 1) << 3) + rw) * RSTR + 256);
    }
    o.b16s = (uint32_t)((64 + rw) * RSTR + ((j3 & 1) << 4));
    o.b8s  = (uint32_t)((64 + rw) * RSTR + 256);

    const int grid = gridDim.x;

    // ---- preamble: d_chi for first tile into buf 0 ----
    {
        long long row = blockIdx.x * (long long)TILE + tid;
        stage_dchi(chi, sm, SM_DC, row, (blockIdx.x < T) && (row < n), tid);
    }
    __syncthreads();

    int p = 0;
    for (long long t = blockIdx.x; t < T; t += grid) {
        const long long row0 = t * TILE;
        const float* dc = (const float*)(sm + SM_DC + (uint32_t)p * 4096);
        float* b1s_p = (float*)(sm + SM_B1S + p * 2048);

        // clamped A row pointers (garbage rows are never stored)
        ARow ar;
        #pragma unroll
        for (int f = 0; f < 4; ++f)
            #pragma unroll
            for (int h = 0; h < 2; ++h) {
                long long r = row0 + mrow + f * 16 + h * 8 + qr;
                if (r > n - 1) r = n - 1;
                ar.p[f * 2 + h] = x + r * FDIM + 4 * qc;
            }

        // ---- MMA (A streamed from global, k-permuted) + a1/b1 epilogue ----
        if (cw == 0)
            compute_tile<0>(ar, dc, whb, wlb, o, bs, b1s_p, a1, row0, n, mrow, qr, qc);
        else
            compute_tile<1>(ar, dc, whb, wlb, o, bs, b1s_p, a1, row0, n, mrow, qr, qc);

        // ---- per-warp: d_chi(t+grid) into buf p^1 (no sync needed) ----
        const long long t2 = t + grid;
        if (t2 < T) {
            long long row2 = t2 * TILE + tid;
            stage_dchi(chi, sm, SM_DC + (uint32_t)(p ^ 1) * 4096, row2, row2 < n, tid);
        }
        __syncthreads();   // b1s[p] + dchi[p^1] ready

        // ---- chi_out(t); overlaps next tile's compute in other warps ----
        chi_out_store(co, chi, b1s_p, row0 + tid, row0 + tid < n, tid);
        p ^= 1;
    }
}

extern "C" void kernel_launch(void* const* d_in, const int* in_sizes, int n_in,
                              void* d_out, int out_size)
{
    int ix = 0, ichi = 1, iW = 3, ib_ = 4;
    long long maxsz = -1;
    for (int i = 0; i < n_in; ++i)
        if ((long long)in_sizes[i] > maxsz) { maxsz = in_sizes[i]; ix = i; }
    long long n = maxsz / FDIM;
    for (int i = 0; i < n_in; ++i) {
        long long s = in_sizes[i];
        if (i == ix) continue;
        if (s == CDIM * CDIM) iW = i;
        else if (s == CDIM)   ib_ = i;
        else if (s == 16 * n) ichi = i;
    }
    const float* x   = (const float*)d_in[ix];
    const float* chi = (const float*)d_in[ichi];
    const float* W   = (const float*)d_in[iW];
    const float* b   = (const float*)d_in[ib_];
    float* a1 = (float*)d_out;
    float* co = a1 + (size_t)n * FDIM;

    long long T = (n + TILE - 1) / TILE;
    int sms = 148;
    cudaDeviceGetAttribute(&sms, cudaDevAttrMultiProcessorCount, 0);
    long long g = 2LL * sms;
    int grid = (int)(T < g ? T : g);

    cudaFuncSetAttribute(ib_mma, cudaFuncAttributeMaxDynamicSharedMemorySize, SMEM_BYTES);
    ib_mma<<<grid, NTHR, SMEM_BYTES>>>(x, chi, W, b, a1, co, n, T);
}